// round 1
// baseline (speedup 1.0000x reference)
#include <cuda_runtime.h>
#include <cuda_bf16.h>
#include <cstddef>

#define BATCH 2
#define CDIM  128
#define HH    56
#define WWD   56
#define PPOS  3136          // H*W
#define LSEQ  3136
#define MR    6272          // BATCH*LSEQ
#define DI    256
#define DS    16
#define NC    49            // scan chunks
#define CL    64            // chunk length (NC*CL = LSEQ)

// ---------------- scratch (static device memory; no allocs) ----------------
__device__ __align__(16) float g_xnorm[2][MR * CDIM];
__device__ __align__(16) float g_xz   [2][MR * 512];
__device__ __align__(16) float g_xs   [2][MR * DI];
__device__ __align__(16) float g_dbl  [2][MR * 40];
__device__ __align__(16) float g_dt   [2][MR * DI];
__device__ __align__(16) float g_ys   [2][MR * DI];
__device__ __align__(16) float g_o    [2][MR * CDIM];
__device__ __align__(16) float g_g    [MR * CDIM];
__device__ __align__(16) float g_lf   [MR * CDIM];
__device__ __align__(16) float g_fused[MR * CDIM];
__device__ __align__(16) float g_Pc [2][NC * BATCH * DI * DS];
__device__ __align__(16) float g_Hc [2][NC * BATCH * DI * DS];
__device__ __align__(16) float g_Hi [2][NC * BATCH * DI * DS];
__device__ float g_msum[BATCH * CDIM];
__device__ float g_attn[BATCH * CDIM];

// ---------------- LayerNorm producing both sequence layouts ----------------
__global__ void ln_kernel(const float* __restrict__ x,
                          const float* __restrict__ hw, const float* __restrict__ hb,
                          const float* __restrict__ vw, const float* __restrict__ vb,
                          float* __restrict__ xh, float* __restrict__ xv)
{
    int p = blockIdx.x, b = blockIdx.y, c = threadIdx.x;   // 128 threads
    float v = x[((size_t)(b * CDIM + c)) * PPOS + p];
    float s = v, sq = v * v;
    #pragma unroll
    for (int off = 16; off; off >>= 1) {
        s  += __shfl_xor_sync(0xffffffffu, s,  off);
        sq += __shfl_xor_sync(0xffffffffu, sq, off);
    }
    __shared__ float ss[4], ssq[4];
    int warp = c >> 5;
    if ((c & 31) == 0) { ss[warp] = s; ssq[warp] = sq; }
    __syncthreads();
    s  = ss[0] + ss[1] + ss[2] + ss[3];
    sq = ssq[0] + ssq[1] + ssq[2] + ssq[3];
    float mean = s * (1.f / 128.f);
    float var  = sq * (1.f / 128.f) - mean * mean;
    float r = rsqrtf(var + 1e-5f);
    float xc = (v - mean) * r;
    int h = p / WWD, w = p % WWD;
    xh[((size_t)(b * LSEQ) + p) * CDIM + c]              = xc * hw[c] + hb[c];
    xv[((size_t)(b * LSEQ) + (w * HH + h)) * CDIM + c]   = xc * vw[c] + vb[c];
}

// ---------------- generic GEMM: C[m,n] = sum_k A[m*lda+k]*B[n*ldb+k] (+bias) ---
__global__ __launch_bounds__(256) void gemm_tn(
    const float* __restrict__ A, const float* __restrict__ Bm,
    const float* __restrict__ bias, float* __restrict__ Cm,
    int M, int N, int K, int lda, int ldb, int ldc)
{
    __shared__ __align__(16) float As[16][68];
    __shared__ __align__(16) float Bs[16][68];
    const int tid = threadIdx.x;
    const int tx = tid & 15;
    const int ty = tid >> 4;
    const int m0 = blockIdx.y << 6;
    const int n0 = blockIdx.x << 6;
    float acc[4][4];
    #pragma unroll
    for (int i = 0; i < 4; i++)
        #pragma unroll
        for (int j = 0; j < 4; j++) acc[i][j] = 0.f;

    const int lr = tid >> 2;         // 0..63
    const int lk = (tid & 3) << 2;   // 0,4,8,12

    for (int k0 = 0; k0 < K; k0 += 16) {
        float4 va = *reinterpret_cast<const float4*>(A + (size_t)(m0 + lr) * lda + k0 + lk);
        float4 vb = make_float4(0.f, 0.f, 0.f, 0.f);
        if (n0 + lr < N)
            vb = *reinterpret_cast<const float4*>(Bm + (size_t)(n0 + lr) * ldb + k0 + lk);
        As[lk][lr] = va.x; As[lk + 1][lr] = va.y; As[lk + 2][lr] = va.z; As[lk + 3][lr] = va.w;
        Bs[lk][lr] = vb.x; Bs[lk + 1][lr] = vb.y; Bs[lk + 2][lr] = vb.z; Bs[lk + 3][lr] = vb.w;
        __syncthreads();
        #pragma unroll
        for (int k = 0; k < 16; k++) {
            float4 ra = *reinterpret_cast<const float4*>(&As[k][ty << 2]);
            float4 rb = *reinterpret_cast<const float4*>(&Bs[k][tx << 2]);
            float a_[4] = {ra.x, ra.y, ra.z, ra.w};
            float b_[4] = {rb.x, rb.y, rb.z, rb.w};
            #pragma unroll
            for (int i = 0; i < 4; i++)
                #pragma unroll
                for (int j = 0; j < 4; j++) acc[i][j] += a_[i] * b_[j];
        }
        __syncthreads();
    }
    #pragma unroll
    for (int j = 0; j < 4; j++) {
        int n = n0 + (tx << 2) + j;
        if (n >= N) continue;
        float bv = bias ? bias[n] : 0.f;
        #pragma unroll
        for (int i = 0; i < 4; i++) {
            int m = m0 + (ty << 2) + i;
            Cm[(size_t)m * ldc + n] = acc[i][j] + bv;
        }
    }
}

// ---------------- causal depthwise conv1d (k=4, pad left 3) + silu ----------
__global__ void conv_silu(const float* __restrict__ xz, const float* __restrict__ cw,
                          const float* __restrict__ cb, float* __restrict__ xs)
{
    int idx = blockIdx.x * 256 + threadIdx.x;
    if (idx >= MR * DI) return;
    int d = idx % DI;
    int m = idx / DI;
    int l = m % LSEQ;
    float acc = cb[d];
    #pragma unroll
    for (int k = 0; k < 4; k++) {
        int ll = l + k - 3;
        if (ll >= 0) acc += xz[(size_t)(m + k - 3) * 512 + d] * cw[d * 4 + k];
    }
    float s = acc / (1.f + expf(-acc));   // silu
    xs[(size_t)m * DI + d] = s;
}

// ---------------- dt = softplus(dbl[:,:8] @ dt_w^T + dt_b) ------------------
__global__ void dt_kernel(const float* __restrict__ dbl, const float* __restrict__ dtw,
                          const float* __restrict__ dtb, float* __restrict__ dt)
{
    int m = blockIdx.x;
    int d = threadIdx.x;   // 256
    __shared__ float sr[8];
    if (d < 8) sr[d] = dbl[(size_t)m * 40 + d];
    __syncthreads();
    float acc = dtb[d];
    #pragma unroll
    for (int r = 0; r < 8; r++) acc += dtw[d * 8 + r] * sr[r];
    float sp = (acc > 20.f) ? acc : log1pf(expf(acc));
    dt[(size_t)m * DI + d] = sp;
}

// ---------------- scan pass A: per-chunk (prod a, partial h) ----------------
__global__ __launch_bounds__(256) void scanA(
    const float* __restrict__ dt, const float* __restrict__ xs,
    const float* __restrict__ dbl, const float* __restrict__ A_log,
    float* __restrict__ Pc, float* __restrict__ Hc)
{
    int d = threadIdx.x;      // 256 = all d
    int chunk = blockIdx.x;   // NC
    int b = blockIdx.y;       // BATCH
    __shared__ float sB[CL][16];
    int base = b * LSEQ + chunk * CL;
    for (int i = d; i < CL * 16; i += 256) {
        int l = i / 16, n = i % 16;
        sB[l][n] = dbl[((size_t)(base + l)) * 40 + 8 + n];
    }
    float a[16];
    #pragma unroll
    for (int n = 0; n < 16; n++) a[n] = -__expf(A_log[d * 16 + n]);
    __syncthreads();
    float h[16], pp[16];
    #pragma unroll
    for (int n = 0; n < 16; n++) { h[n] = 0.f; pp[n] = 1.f; }
    for (int l = 0; l < CL; l++) {
        float dtv = dt[(size_t)(base + l) * DI + d];
        float xsv = xs[(size_t)(base + l) * DI + d];
        float du = dtv * xsv;
        #pragma unroll
        for (int n = 0; n < 16; n++) {
            float e = __expf(dtv * a[n]);
            pp[n] *= e;
            h[n] = e * h[n] + du * sB[l][n];
        }
    }
    size_t o = (((size_t)chunk * BATCH + b) * DI + d) * DS;
    #pragma unroll
    for (int n = 0; n < 16; n++) { Pc[o + n] = pp[n]; Hc[o + n] = h[n]; }
}

// ---------------- scan pass B: cross-chunk combine --------------------------
__global__ void scanB(const float* __restrict__ Pc, const float* __restrict__ Hc,
                      float* __restrict__ Hi)
{
    int idx = blockIdx.x * 256 + threadIdx.x;   // b*4096 + d*16 + n
    if (idx >= BATCH * DI * DS) return;
    int b = idx / (DI * DS);
    int dn = idx % (DI * DS);
    float h = 0.f;
    for (int c = 0; c < NC; c++) {
        size_t o = ((size_t)c * BATCH + b) * (DI * DS) + dn;
        Hi[o] = h;
        h = Pc[o] * h + Hc[o];
    }
}

// ---------------- scan pass C: replay chunks, emit y ------------------------
__global__ __launch_bounds__(256) void scanC(
    const float* __restrict__ dt, const float* __restrict__ xs,
    const float* __restrict__ dbl, const float* __restrict__ A_log,
    const float* __restrict__ Hi, float* __restrict__ ysout)
{
    int d = threadIdx.x;
    int chunk = blockIdx.x;
    int b = blockIdx.y;
    __shared__ float sBC[CL][32];
    int base = b * LSEQ + chunk * CL;
    for (int i = d; i < CL * 32; i += 256) {
        int l = i / 32, j = i % 32;
        sBC[l][j] = dbl[((size_t)(base + l)) * 40 + 8 + j];
    }
    float a[16];
    #pragma unroll
    for (int n = 0; n < 16; n++) a[n] = -__expf(A_log[d * 16 + n]);
    float h[16];
    size_t o = (((size_t)chunk * BATCH + b) * DI + d) * DS;
    #pragma unroll
    for (int n = 0; n < 16; n++) h[n] = Hi[o + n];
    __syncthreads();
    for (int l = 0; l < CL; l++) {
        float dtv = dt[(size_t)(base + l) * DI + d];
        float xsv = xs[(size_t)(base + l) * DI + d];
        float du = dtv * xsv;
        float y = 0.f;
        #pragma unroll
        for (int n = 0; n < 16; n++) {
            float e = __expf(dtv * a[n]);
            h[n] = e * h[n] + du * sBC[l][n];
            y += h[n] * sBC[l][16 + n];
        }
        ysout[(size_t)(base + l) * DI + d] = y;
    }
}

// ---------------- gating: yg = (ys + xs*D) * silu(z) ------------------------
__global__ void gate_kernel(float* __restrict__ ys, const float* __restrict__ xs,
                            const float* __restrict__ xz, const float* __restrict__ Dp)
{
    int idx = blockIdx.x * 256 + threadIdx.x;
    if (idx >= MR * DI) return;
    int d = idx % DI;
    int m = idx / DI;
    float z = xz[(size_t)m * 512 + 256 + d];
    float sz = z / (1.f + expf(-z));
    ys[idx] = (ys[idx] + xs[idx] * Dp[d]) * sz;
}

// ---------------- depthwise 3x3 conv + exact GELU ---------------------------
__global__ void dwgelu(const float* __restrict__ x, const float* __restrict__ dww,
                       const float* __restrict__ dwb, float* __restrict__ g)
{
    int idx = blockIdx.x * 256 + threadIdx.x;
    if (idx >= BATCH * CDIM * PPOS) return;
    int p = idx % PPOS;
    int c = (idx / PPOS) % CDIM;
    int b = idx / (PPOS * CDIM);
    int h = p / WWD, w = p % WWD;
    float acc = dwb[c];
    #pragma unroll
    for (int kh = 0; kh < 3; kh++) {
        int hh = h + kh - 1;
        if (hh < 0 || hh >= HH) continue;
        #pragma unroll
        for (int kw = 0; kw < 3; kw++) {
            int ww = w + kw - 1;
            if (ww < 0 || ww >= WWD) continue;
            acc += x[((size_t)(b * CDIM + c)) * PPOS + hh * WWD + ww] * dww[c * 9 + kh * 3 + kw];
        }
    }
    float ge = 0.5f * acc * (1.f + erff(acc * 0.70710678118654752f));
    g[((size_t)(b * PPOS + p)) * CDIM + c] = ge;   // [b][p][c] layout
}

// ---------------- fuse oh+ov+lf, partial spatial mean -----------------------
__global__ void fuse_kernel(const float* __restrict__ oh, const float* __restrict__ ov,
                            const float* __restrict__ lf, float* __restrict__ fused,
                            float* __restrict__ msum)
{
    int c = threadIdx.x;        // 128
    int pc = blockIdx.x;        // 98 chunks of 32
    int b = blockIdx.y;
    float s = 0.f;
    for (int i = 0; i < 32; i++) {
        int p = pc * 32 + i;
        int pv = (p % WWD) * HH + p / WWD;
        float f = oh[((size_t)(b * LSEQ + p)) * CDIM + c]
                + ov[((size_t)(b * LSEQ + pv)) * CDIM + c]
                + lf[((size_t)(b * PPOS + p)) * CDIM + c];
        fused[((size_t)(b * PPOS + p)) * CDIM + c] = f;
        s += f;
    }
    atomicAdd(&msum[b * CDIM + c], s);
}

__global__ void zero_kernel(float* __restrict__ msum)
{
    msum[threadIdx.x] = 0.f;   // 256 threads
}

// ---------------- channel attention -----------------------------------------
__global__ void attn_kernel(const float* __restrict__ msum, const float* __restrict__ fc1,
                            const float* __restrict__ fc2, float* __restrict__ attn)
{
    __shared__ float sm[BATCH][CDIM];
    __shared__ float t1[BATCH][32];
    int t = threadIdx.x;  // 256
    {
        int b = t / CDIM, c = t % CDIM;
        sm[b][c] = msum[t] * (1.f / (float)PPOS);
    }
    __syncthreads();
    if (t < 64) {
        int b = t / 32, i = t % 32;
        float acc = 0.f;
        #pragma unroll 4
        for (int c = 0; c < CDIM; c++) acc += sm[b][c] * fc1[i * CDIM + c];
        t1[b][i] = fmaxf(acc, 0.f);
    }
    __syncthreads();
    {
        int b = t / CDIM, c = t % CDIM;
        float acc = 0.f;
        #pragma unroll
        for (int i = 0; i < 32; i++) acc += t1[b][i] * fc2[c * 32 + i];
        attn[t] = 1.f / (1.f + expf(-acc));
    }
}

// ---------------- final: out = fused*attn + x --------------------------------
__global__ void final_kernel(const float* __restrict__ fused, const float* __restrict__ attn,
                             const float* __restrict__ x, float* __restrict__ out)
{
    int idx = blockIdx.x * 256 + threadIdx.x;
    if (idx >= BATCH * CDIM * PPOS) return;
    int p = idx % PPOS;
    int c = (idx / PPOS) % CDIM;
    int b = idx / (PPOS * CDIM);
    float f = fused[((size_t)(b * PPOS + p)) * CDIM + c];
    out[idx] = f * attn[b * CDIM + c] + x[idx];
}

// ============================================================================
extern "C" void kernel_launch(void* const* d_in, const int* in_sizes, int n_in,
                              void* d_out, int out_size)
{
    const float* x       = (const float*)d_in[0];
    const float* norm_hw = (const float*)d_in[1];
    const float* norm_hb = (const float*)d_in[2];
    const float* norm_vw = (const float*)d_in[3];
    const float* norm_vb = (const float*)d_in[4];
    const float* dw_w    = (const float*)d_in[5];
    const float* dw_b    = (const float*)d_in[6];
    const float* pw_w    = (const float*)d_in[7];
    const float* pw_b    = (const float*)d_in[8];
    const float* in_w_[2]    = {(const float*)d_in[9],  (const float*)d_in[18]};
    const float* conv_w_[2]  = {(const float*)d_in[10], (const float*)d_in[19]};
    const float* conv_b_[2]  = {(const float*)d_in[11], (const float*)d_in[20]};
    const float* xproj_w_[2] = {(const float*)d_in[12], (const float*)d_in[21]};
    const float* dt_w_[2]    = {(const float*)d_in[13], (const float*)d_in[22]};
    const float* dt_b_[2]    = {(const float*)d_in[14], (const float*)d_in[23]};
    const float* A_log_[2]   = {(const float*)d_in[15], (const float*)d_in[24]};
    const float* D_[2]       = {(const float*)d_in[16], (const float*)d_in[25]};
    const float* out_w_[2]   = {(const float*)d_in[17], (const float*)d_in[26]};
    const float* fc1     = (const float*)d_in[27];
    const float* fc2     = (const float*)d_in[28];

    void* p;
    cudaGetSymbolAddress(&p, g_xnorm); float* xnorm = (float*)p;
    cudaGetSymbolAddress(&p, g_xz);    float* xz    = (float*)p;
    cudaGetSymbolAddress(&p, g_xs);    float* xs    = (float*)p;
    cudaGetSymbolAddress(&p, g_dbl);   float* dbl   = (float*)p;
    cudaGetSymbolAddress(&p, g_dt);    float* dt    = (float*)p;
    cudaGetSymbolAddress(&p, g_ys);    float* ys    = (float*)p;
    cudaGetSymbolAddress(&p, g_o);     float* ob    = (float*)p;
    cudaGetSymbolAddress(&p, g_g);     float* gbuf  = (float*)p;
    cudaGetSymbolAddress(&p, g_lf);    float* lfb   = (float*)p;
    cudaGetSymbolAddress(&p, g_fused); float* fused = (float*)p;
    cudaGetSymbolAddress(&p, g_Pc);    float* Pc    = (float*)p;
    cudaGetSymbolAddress(&p, g_Hc);    float* Hc    = (float*)p;
    cudaGetSymbolAddress(&p, g_Hi);    float* Hi    = (float*)p;
    cudaGetSymbolAddress(&p, g_msum);  float* msum  = (float*)p;
    cudaGetSymbolAddress(&p, g_attn);  float* attn  = (float*)p;

    const int EW = (MR * DI + 255) / 256;        // elementwise grid over M*256
    const int EC = (BATCH * CDIM * PPOS + 255) / 256;
    const size_t SCAN_STRIDE = (size_t)NC * BATCH * DI * DS;

    // local-feature branch
    dwgelu<<<EC, 256>>>(x, dw_w, dw_b, gbuf);
    gemm_tn<<<dim3(2, MR / 64), 256>>>(gbuf, pw_w, pw_b, lfb, MR, 128, 128, 128, 128, 128);

    // layernorm (both sequence layouts)
    ln_kernel<<<dim3(PPOS, BATCH), 128>>>(x, norm_hw, norm_hb, norm_vw, norm_vb,
                                          xnorm, xnorm + (size_t)MR * CDIM);

    for (int dir = 0; dir < 2; dir++) {
        float* xnorm_d = xnorm + (size_t)dir * MR * CDIM;
        float* xz_d    = xz    + (size_t)dir * MR * 512;
        float* xs_d    = xs    + (size_t)dir * MR * DI;
        float* dbl_d   = dbl   + (size_t)dir * MR * 40;
        float* dt_d    = dt    + (size_t)dir * MR * DI;
        float* ys_d    = ys    + (size_t)dir * MR * DI;
        float* o_d     = ob    + (size_t)dir * MR * CDIM;
        float* Pc_d    = Pc + dir * SCAN_STRIDE;
        float* Hc_d    = Hc + dir * SCAN_STRIDE;
        float* Hi_d    = Hi + dir * SCAN_STRIDE;

        gemm_tn<<<dim3(8, MR / 64), 256>>>(xnorm_d, in_w_[dir], nullptr, xz_d,
                                           MR, 512, 128, 128, 128, 512);
        conv_silu<<<EW, 256>>>(xz_d, conv_w_[dir], conv_b_[dir], xs_d);
        gemm_tn<<<dim3(1, MR / 64), 256>>>(xs_d, xproj_w_[dir], nullptr, dbl_d,
                                           MR, 40, 256, 256, 256, 40);
        dt_kernel<<<MR, 256>>>(dbl_d, dt_w_[dir], dt_b_[dir], dt_d);
        scanA<<<dim3(NC, BATCH), 256>>>(dt_d, xs_d, dbl_d, A_log_[dir], Pc_d, Hc_d);
        scanB<<<(BATCH * DI * DS + 255) / 256, 256>>>(Pc_d, Hc_d, Hi_d);
        scanC<<<dim3(NC, BATCH), 256>>>(dt_d, xs_d, dbl_d, A_log_[dir], Hi_d, ys_d);
        gate_kernel<<<EW, 256>>>(ys_d, xs_d, xz_d, D_[dir]);
        gemm_tn<<<dim3(2, MR / 64), 256>>>(ys_d, out_w_[dir], nullptr, o_d,
                                           MR, 128, 256, 256, 256, 128);
    }

    zero_kernel<<<1, 256>>>(msum);
    fuse_kernel<<<dim3(PPOS / 32, BATCH), 128>>>(ob, ob + (size_t)MR * CDIM, lfb, fused, msum);
    attn_kernel<<<1, 256>>>(msum, fc1, fc2, attn);
    final_kernel<<<EC, 256>>>(fused, attn, x, (float*)d_out);
}

// round 2
// speedup vs baseline: 1.4773x; 1.4773x over previous
#include <cuda_runtime.h>
#include <cuda_bf16.h>
#include <cstddef>

#define BATCH 2
#define CDIM  128
#define HH    56
#define WWD   56
#define PPOS  3136
#define LSEQ  3136
#define MR    6272
#define DI    256
#define DS    16
#define NC    49
#define CL    64

// ---------------- scratch ----------------
__device__ __align__(16) float g_xnorm[2][MR * CDIM];
__device__ __align__(16) float g_xz   [2][MR * 512];
__device__ __align__(16) float g_xs   [2][MR * DI];
__device__ __align__(16) float g_dbl  [2][MR * 40];
__device__ __align__(16) float g_dt   [2][MR * DI];
__device__ __align__(16) float g_ys   [2][MR * DI];
__device__ __align__(16) float g_o    [2][MR * CDIM];
__device__ __align__(16) float g_g    [MR * CDIM];
__device__ __align__(16) float g_lf   [MR * CDIM];
__device__ __align__(16) float g_fused[MR * CDIM];
__device__ __align__(16) float g_Pc [2][NC * BATCH * DI * DS];
__device__ __align__(16) float g_Hc [2][NC * BATCH * DI * DS];
__device__ __align__(16) float g_Hi [2][NC * BATCH * DI * DS];
__device__ __align__(16) float g_psum[BATCH * 98 * CDIM];
__device__ float g_attn[BATCH * CDIM];

// ========== LayerNorm: coalesced via smem tile, both layouts out ==========
__global__ __launch_bounds__(256) void ln_kernel(
    const float* __restrict__ x,
    const float* __restrict__ hw, const float* __restrict__ hb,
    const float* __restrict__ vw, const float* __restrict__ vb,
    float* __restrict__ xh, float* __restrict__ xv)
{
    __shared__ float sx[128][33];
    __shared__ float part[8][33];
    __shared__ float partq[8][33];
    __shared__ float mu[32], rs[32];
    int t = threadIdx.x;
    int p0 = blockIdx.x * 32;
    int b  = blockIdx.y;
    int pl = t & 31, c8 = t >> 5;
    float s = 0.f, sq = 0.f;
    #pragma unroll
    for (int pass = 0; pass < 16; pass++) {
        int c = pass * 8 + c8;
        float v = x[((size_t)(b * 128 + c)) * PPOS + p0 + pl];
        sx[c][pl] = v;
        s += v; sq += v * v;
    }
    part[c8][pl] = s; partq[c8][pl] = sq;
    __syncthreads();
    if (t < 32) {
        float S = 0.f, Q = 0.f;
        #pragma unroll
        for (int r = 0; r < 8; r++) { S += part[r][t]; Q += partq[r][t]; }
        float mean = S * (1.f / 128.f);
        float var  = Q * (1.f / 128.f) - mean * mean;
        mu[t] = mean;
        rs[t] = rsqrtf(var + 1e-5f);
    }
    __syncthreads();
    int c = t & 127, ph = t >> 7;
    float whh = hw[c], bhh = hb[c], wvv = vw[c], bvv = vb[c];
    #pragma unroll
    for (int pass = 0; pass < 16; pass++) {
        int pl2 = pass * 2 + ph;
        int p = p0 + pl2;
        float xc = (sx[c][pl2] - mu[pl2]) * rs[pl2];
        int h = p / WWD, w = p % WWD;
        xh[((size_t)b * LSEQ + p) * 128 + c]              = xc * whh + bhh;
        xv[((size_t)b * LSEQ + (w * HH + h)) * 128 + c]   = xc * wvv + bvv;
    }
}

// ========== GEMM 128x64 tile, 8x4/thread, double-buffered ==========
// C[m,n] = sum_k A[m*K+k]*B[n*K+k] (+bias), dir = blockIdx.z
__global__ __launch_bounds__(256) void gemm128(
    const float* __restrict__ Abase,
    const float* __restrict__ B0, const float* __restrict__ B1,
    const float* __restrict__ bias0, const float* __restrict__ bias1,
    float* __restrict__ Cbase,
    int N, int K, size_t dsA, size_t dsC)
{
    const int dir = blockIdx.z;
    const float* A  = Abase + (size_t)dir * dsA;
    const float* Bw = dir ? B1 : B0;
    const float* bi = dir ? bias1 : bias0;
    float* C = Cbase + (size_t)dir * dsC;
    const int m0 = blockIdx.y * 128;
    const int n0 = blockIdx.x * 64;

    __shared__ float As[2][16][132];
    __shared__ float Bs[2][16][68];

    const int t = threadIdx.x;
    const int tx = t & 15, ty = t >> 4;
    const int aRow = t >> 1;
    const int aK   = (t & 1) * 8;
    const int bRow = t >> 2;
    const int bK   = (t & 3) * 4;

    const float* Aptr = A + (size_t)(m0 + aRow) * K + aK;
    const float* Bptr = Bw + (size_t)(n0 + bRow) * K + bK;

    float4 pa0 = *(const float4*)(Aptr);
    float4 pa1 = *(const float4*)(Aptr + 4);
    float4 pb  = *(const float4*)(Bptr);

    float acc[8][4];
    #pragma unroll
    for (int i = 0; i < 8; i++)
        #pragma unroll
        for (int j = 0; j < 4; j++) acc[i][j] = 0.f;

    As[0][aK + 0][aRow] = pa0.x; As[0][aK + 1][aRow] = pa0.y;
    As[0][aK + 2][aRow] = pa0.z; As[0][aK + 3][aRow] = pa0.w;
    As[0][aK + 4][aRow] = pa1.x; As[0][aK + 5][aRow] = pa1.y;
    As[0][aK + 6][aRow] = pa1.z; As[0][aK + 7][aRow] = pa1.w;
    Bs[0][bK + 0][bRow] = pb.x;  Bs[0][bK + 1][bRow] = pb.y;
    Bs[0][bK + 2][bRow] = pb.z;  Bs[0][bK + 3][bRow] = pb.w;
    __syncthreads();

    const int ntiles = K >> 4;
    int buf = 0;
    for (int kt = 0; kt < ntiles; kt++) {
        bool more = (kt + 1 < ntiles);
        if (more) {
            pa0 = *(const float4*)(Aptr + (kt + 1) * 16);
            pa1 = *(const float4*)(Aptr + (kt + 1) * 16 + 4);
            pb  = *(const float4*)(Bptr + (kt + 1) * 16);
        }
        #pragma unroll
        for (int k = 0; k < 16; k++) {
            float4 a0 = *(const float4*)&As[buf][k][ty * 8];
            float4 a1 = *(const float4*)&As[buf][k][ty * 8 + 4];
            float4 bb = *(const float4*)&Bs[buf][k][tx * 4];
            float av[8] = {a0.x, a0.y, a0.z, a0.w, a1.x, a1.y, a1.z, a1.w};
            float bv[4] = {bb.x, bb.y, bb.z, bb.w};
            #pragma unroll
            for (int i = 0; i < 8; i++)
                #pragma unroll
                for (int j = 0; j < 4; j++) acc[i][j] = fmaf(av[i], bv[j], acc[i][j]);
        }
        if (more) {
            int nb = buf ^ 1;
            As[nb][aK + 0][aRow] = pa0.x; As[nb][aK + 1][aRow] = pa0.y;
            As[nb][aK + 2][aRow] = pa0.z; As[nb][aK + 3][aRow] = pa0.w;
            As[nb][aK + 4][aRow] = pa1.x; As[nb][aK + 5][aRow] = pa1.y;
            As[nb][aK + 6][aRow] = pa1.z; As[nb][aK + 7][aRow] = pa1.w;
            Bs[nb][bK + 0][bRow] = pb.x;  Bs[nb][bK + 1][bRow] = pb.y;
            Bs[nb][bK + 2][bRow] = pb.z;  Bs[nb][bK + 3][bRow] = pb.w;
        }
        __syncthreads();
        buf ^= 1;
    }

    float4 bvv = make_float4(0.f, 0.f, 0.f, 0.f);
    if (bi) bvv = *(const float4*)(bi + n0 + tx * 4);
    #pragma unroll
    for (int i = 0; i < 8; i++) {
        float4 v;
        v.x = acc[i][0] + bvv.x; v.y = acc[i][1] + bvv.y;
        v.z = acc[i][2] + bvv.z; v.w = acc[i][3] + bvv.w;
        *(float4*)(C + (size_t)(m0 + ty * 8 + i) * N + n0 + tx * 4) = v;
    }
}

// ========== x_proj GEMM (N=40, K=256) + fused dt projection/softplus ==========
__global__ __launch_bounds__(256) void xproj_dt(
    const float* __restrict__ xsg,
    const float* __restrict__ W0, const float* __restrict__ W1,
    const float* __restrict__ dtw0, const float* __restrict__ dtw1,
    const float* __restrict__ dtb0, const float* __restrict__ dtb1,
    float* __restrict__ dblg, float* __restrict__ dtg)
{
    const int dir = blockIdx.z;
    const float* A   = xsg + (size_t)dir * MR * DI;
    const float* Bw  = dir ? W1 : W0;
    const float* dtw = dir ? dtw1 : dtw0;
    const float* dtb = dir ? dtb1 : dtb0;
    float* dbl = dblg + (size_t)dir * MR * 40;
    float* dto = dtg  + (size_t)dir * MR * DI;
    const int m0 = blockIdx.y * 64;
    const int K = 256;

    __shared__ float As[2][16][68];
    __shared__ float Bs[2][16][68];
    __shared__ float sdt[64][9];

    const int t = threadIdx.x;
    const int tx = t & 15, ty = t >> 4;
    const int aRow = t >> 2;
    const int aK   = (t & 3) * 4;

    const float* Aptr = A + (size_t)(m0 + aRow) * K + aK;
    const float* Bptr = Bw + (size_t)aRow * K + aK;   // same (row,k) split; row<40 valid
    const bool bValid = aRow < 40;

    float4 pa = *(const float4*)(Aptr);
    float4 pb = bValid ? *(const float4*)(Bptr) : make_float4(0, 0, 0, 0);

    float acc[4][4];
    #pragma unroll
    for (int i = 0; i < 4; i++)
        #pragma unroll
        for (int j = 0; j < 4; j++) acc[i][j] = 0.f;

    As[0][aK + 0][aRow] = pa.x; As[0][aK + 1][aRow] = pa.y;
    As[0][aK + 2][aRow] = pa.z; As[0][aK + 3][aRow] = pa.w;
    Bs[0][aK + 0][aRow] = pb.x; Bs[0][aK + 1][aRow] = pb.y;
    Bs[0][aK + 2][aRow] = pb.z; Bs[0][aK + 3][aRow] = pb.w;
    __syncthreads();

    int buf = 0;
    for (int kt = 0; kt < 16; kt++) {
        bool more = (kt + 1 < 16);
        if (more) {
            pa = *(const float4*)(Aptr + (kt + 1) * 16);
            pb = bValid ? *(const float4*)(Bptr + (kt + 1) * 16) : make_float4(0, 0, 0, 0);
        }
        #pragma unroll
        for (int k = 0; k < 16; k++) {
            float4 a = *(const float4*)&As[buf][k][ty * 4];
            float4 b = *(const float4*)&Bs[buf][k][tx * 4];
            float av[4] = {a.x, a.y, a.z, a.w};
            float bv[4] = {b.x, b.y, b.z, b.w};
            #pragma unroll
            for (int i = 0; i < 4; i++)
                #pragma unroll
                for (int j = 0; j < 4; j++) acc[i][j] = fmaf(av[i], bv[j], acc[i][j]);
        }
        if (more) {
            int nb = buf ^ 1;
            As[nb][aK + 0][aRow] = pa.x; As[nb][aK + 1][aRow] = pa.y;
            As[nb][aK + 2][aRow] = pa.z; As[nb][aK + 3][aRow] = pa.w;
            Bs[nb][aK + 0][aRow] = pb.x; Bs[nb][aK + 1][aRow] = pb.y;
            Bs[nb][aK + 2][aRow] = pb.z; Bs[nb][aK + 3][aRow] = pb.w;
        }
        __syncthreads();
        buf ^= 1;
    }

    // write dbl (n<40), stage dt-rank columns
    if (tx < 10) {
        #pragma unroll
        for (int i = 0; i < 4; i++) {
            float4 v = make_float4(acc[i][0], acc[i][1], acc[i][2], acc[i][3]);
            *(float4*)(dbl + (size_t)(m0 + ty * 4 + i) * 40 + tx * 4) = v;
        }
    }
    if (tx < 2) {
        #pragma unroll
        for (int i = 0; i < 4; i++)
            #pragma unroll
            for (int j = 0; j < 4; j++)
                sdt[ty * 4 + i][tx * 4 + j] = acc[i][j];
    }
    __syncthreads();

    // dt: each thread owns one d across all 64 rows
    int d = t;
    float w[8];
    #pragma unroll
    for (int r = 0; r < 8; r++) w[r] = dtw[d * 8 + r];
    float db = dtb[d];
    for (int row = 0; row < 64; row++) {
        float s = db;
        #pragma unroll
        for (int r = 0; r < 8; r++) s = fmaf(sdt[row][r], w[r], s);
        float sp = (s > 20.f) ? s : log1pf(__expf(s));
        dto[(size_t)(m0 + row) * DI + d] = sp;
    }
}

// ========== causal conv1d k=4 + silu, float4, both dirs ==========
__global__ __launch_bounds__(256) void conv_silu(
    const float* __restrict__ xzg,
    const float* __restrict__ cw0, const float* __restrict__ cw1,
    const float* __restrict__ cb0, const float* __restrict__ cb1,
    float* __restrict__ xsg)
{
    const int dir = blockIdx.y;
    const float* xz = xzg + (size_t)dir * MR * 512;
    const float* cw = dir ? cw1 : cw0;
    const float* cb = dir ? cb1 : cb0;
    float* xs = xsg + (size_t)dir * MR * DI;
    int idx = blockIdx.x * 256 + threadIdx.x;      // over MR*DI/4
    if (idx >= MR * (DI / 4)) return;
    int d4 = idx & 63;
    int m  = idx >> 6;
    int l  = m % LSEQ;
    int d  = d4 * 4;
    float4 acc = *(const float4*)(cb + d);
    float w0[4], w1[4], w2[4], w3[4];
    #pragma unroll
    for (int k = 0; k < 4; k++) {
        w0[k] = cw[(d + 0) * 4 + k]; w1[k] = cw[(d + 1) * 4 + k];
        w2[k] = cw[(d + 2) * 4 + k]; w3[k] = cw[(d + 3) * 4 + k];
    }
    #pragma unroll
    for (int k = 0; k < 4; k++) {
        int ll = l + k - 3;
        if (ll >= 0) {
            float4 v = *(const float4*)(xz + (size_t)(m + k - 3) * 512 + d);
            acc.x = fmaf(v.x, w0[k], acc.x);
            acc.y = fmaf(v.y, w1[k], acc.y);
            acc.z = fmaf(v.z, w2[k], acc.z);
            acc.w = fmaf(v.w, w3[k], acc.w);
        }
    }
    float4 o;
    o.x = acc.x / (1.f + __expf(-acc.x));
    o.y = acc.y / (1.f + __expf(-acc.y));
    o.z = acc.z / (1.f + __expf(-acc.z));
    o.w = acc.w / (1.f + __expf(-acc.w));
    *(float4*)(xs + (size_t)m * DI + d) = o;
}

// ========== scan pass A ==========
__global__ __launch_bounds__(256) void scanA(
    const float* __restrict__ dtg, const float* __restrict__ xsg,
    const float* __restrict__ dblg,
    const float* __restrict__ Al0, const float* __restrict__ Al1,
    float* __restrict__ Pcg, float* __restrict__ Hcg)
{
    int d = threadIdx.x, chunk = blockIdx.x, b = blockIdx.y, dir = blockIdx.z;
    const float* dt  = dtg + (size_t)dir * MR * DI;
    const float* xs  = xsg + (size_t)dir * MR * DI;
    const float* dbl = dblg + (size_t)dir * MR * 40;
    const float* Al  = dir ? Al1 : Al0;
    float* Pc = Pcg + (size_t)dir * NC * BATCH * DI * DS;
    float* Hc = Hcg + (size_t)dir * NC * BATCH * DI * DS;
    __shared__ float sB[CL][16];
    int base = b * LSEQ + chunk * CL;
    for (int i = d; i < CL * 16; i += 256) {
        int l = i >> 4, n = i & 15;
        sB[l][n] = dbl[(size_t)(base + l) * 40 + 8 + n];
    }
    float a[16]; bool fast = true;
    #pragma unroll
    for (int n = 0; n < 16; n++) {
        a[n] = -__expf(Al[d * 16 + n]);
        fast = fast && (fabsf(a[n] + (float)(n + 1)) <= 1e-4f * (n + 1));
    }
    __syncthreads();
    float h[16], pp[16];
    #pragma unroll
    for (int n = 0; n < 16; n++) { h[n] = 0.f; pp[n] = 1.f; }
    if (fast) {
        for (int l = 0; l < CL; l++) {
            float dtv = dt[(size_t)(base + l) * DI + d];
            float xsv = xs[(size_t)(base + l) * DI + d];
            float du = dtv * xsv;
            float e1 = __expf(-dtv);
            float e[16]; e[0] = e1;
            #pragma unroll
            for (int n = 1; n < 16; n++) e[n] = e[n - 1] * e1;
            #pragma unroll
            for (int n = 0; n < 16; n++) {
                pp[n] *= e[n];
                h[n] = fmaf(e[n], h[n], du * sB[l][n]);
            }
        }
    } else {
        for (int l = 0; l < CL; l++) {
            float dtv = dt[(size_t)(base + l) * DI + d];
            float xsv = xs[(size_t)(base + l) * DI + d];
            float du = dtv * xsv;
            #pragma unroll
            for (int n = 0; n < 16; n++) {
                float e = __expf(dtv * a[n]);
                pp[n] *= e;
                h[n] = fmaf(e, h[n], du * sB[l][n]);
            }
        }
    }
    size_t o = (((size_t)chunk * BATCH + b) * DI + d) * DS;
    #pragma unroll
    for (int n = 0; n < 16; n++) { Pc[o + n] = pp[n]; Hc[o + n] = h[n]; }
}

// ========== scan pass B ==========
__global__ void scanB(const float* __restrict__ Pcg, const float* __restrict__ Hcg,
                      float* __restrict__ Hig)
{
    int dir = blockIdx.y;
    const float* Pc = Pcg + (size_t)dir * NC * BATCH * DI * DS;
    const float* Hc = Hcg + (size_t)dir * NC * BATCH * DI * DS;
    float* Hi = Hig + (size_t)dir * NC * BATCH * DI * DS;
    int idx = blockIdx.x * 256 + threadIdx.x;
    if (idx >= BATCH * DI * DS) return;
    float h = 0.f;
    for (int c = 0; c < NC; c++) {
        size_t o = (size_t)c * (BATCH * DI * DS) + idx;
        Hi[o] = h;
        h = fmaf(Pc[o], h, Hc[o]);
    }
}

// ========== scan pass C + gate fused ==========
__global__ __launch_bounds__(256) void scanC(
    const float* __restrict__ dtg, const float* __restrict__ xsg,
    const float* __restrict__ dblg, const float* __restrict__ xzg,
    const float* __restrict__ Al0, const float* __restrict__ Al1,
    const float* __restrict__ D0, const float* __restrict__ D1,
    const float* __restrict__ Hig, float* __restrict__ ysg)
{
    int d = threadIdx.x, chunk = blockIdx.x, b = blockIdx.y, dir = blockIdx.z;
    const float* dt  = dtg + (size_t)dir * MR * DI;
    const float* xs  = xsg + (size_t)dir * MR * DI;
    const float* dbl = dblg + (size_t)dir * MR * 40;
    const float* xz  = xzg + (size_t)dir * MR * 512;
    const float* Al  = dir ? Al1 : Al0;
    const float* Dp  = dir ? D1 : D0;
    const float* Hi  = Hig + (size_t)dir * NC * BATCH * DI * DS;
    float* ys = ysg + (size_t)dir * MR * DI;
    __shared__ float sBC[CL][32];
    int base = b * LSEQ + chunk * CL;
    for (int i = d; i < CL * 32; i += 256) {
        int l = i >> 5, j = i & 31;
        sBC[l][j] = dbl[(size_t)(base + l) * 40 + 8 + j];
    }
    float a[16]; bool fast = true;
    #pragma unroll
    for (int n = 0; n < 16; n++) {
        a[n] = -__expf(Al[d * 16 + n]);
        fast = fast && (fabsf(a[n] + (float)(n + 1)) <= 1e-4f * (n + 1));
    }
    float Dd = Dp[d];
    float h[16];
    size_t o = (((size_t)chunk * BATCH + b) * DI + d) * DS;
    #pragma unroll
    for (int n = 0; n < 16; n++) h[n] = Hi[o + n];
    __syncthreads();
    if (fast) {
        for (int l = 0; l < CL; l++) {
            float dtv = dt[(size_t)(base + l) * DI + d];
            float xsv = xs[(size_t)(base + l) * DI + d];
            float zv  = xz[(size_t)(base + l) * 512 + 256 + d];
            float du = dtv * xsv;
            float e1 = __expf(-dtv);
            float e[16]; e[0] = e1;
            #pragma unroll
            for (int n = 1; n < 16; n++) e[n] = e[n - 1] * e1;
            float y = 0.f;
            #pragma unroll
            for (int n = 0; n < 16; n++) {
                h[n] = fmaf(e[n], h[n], du * sBC[l][n]);
                y = fmaf(h[n], sBC[l][16 + n], y);
            }
            float sz = zv / (1.f + __expf(-zv));
            ys[(size_t)(base + l) * DI + d] = (y + xsv * Dd) * sz;
        }
    } else {
        for (int l = 0; l < CL; l++) {
            float dtv = dt[(size_t)(base + l) * DI + d];
            float xsv = xs[(size_t)(base + l) * DI + d];
            float zv  = xz[(size_t)(base + l) * 512 + 256 + d];
            float du = dtv * xsv;
            float y = 0.f;
            #pragma unroll
            for (int n = 0; n < 16; n++) {
                float e = __expf(dtv * a[n]);
                h[n] = fmaf(e, h[n], du * sBC[l][n]);
                y = fmaf(h[n], sBC[l][16 + n], y);
            }
            float sz = zv / (1.f + __expf(-zv));
            ys[(size_t)(base + l) * DI + d] = (y + xsv * Dd) * sz;
        }
    }
}

// ========== depthwise 3x3 + GELU, coalesced both sides via smem tile ==========
__global__ __launch_bounds__(256) void dwgelu(
    const float* __restrict__ x, const float* __restrict__ dww,
    const float* __restrict__ dwb, float* __restrict__ g)
{
    __shared__ float sg[128][33];
    int t = threadIdx.x;
    int p0 = blockIdx.x * 32;
    int b  = blockIdx.y;
    int pl = t & 31, c8 = t >> 5;
    int p = p0 + pl;
    int h = p / WWD, w = p % WWD;
    #pragma unroll
    for (int pass = 0; pass < 16; pass++) {
        int c = pass * 8 + c8;
        const float* xb = x + ((size_t)(b * 128 + c)) * PPOS;
        float acc = dwb[c];
        #pragma unroll
        for (int kh = 0; kh < 3; kh++) {
            int hh = h + kh - 1;
            if (hh < 0 || hh >= HH) continue;
            #pragma unroll
            for (int kw = 0; kw < 3; kw++) {
                int ww = w + kw - 1;
                if (ww < 0 || ww >= WWD) continue;
                acc = fmaf(xb[hh * WWD + ww], dww[c * 9 + kh * 3 + kw], acc);
            }
        }
        sg[c][pl] = 0.5f * acc * (1.f + erff(acc * 0.70710678118654752f));
    }
    __syncthreads();
    int c = t & 127, ph = t >> 7;
    #pragma unroll
    for (int pass = 0; pass < 16; pass++) {
        int pl2 = pass * 2 + ph;
        g[((size_t)(b * PPOS + p0 + pl2)) * 128 + c] = sg[c][pl2];
    }
}

// ========== fuse oh+ov+lf, partial sums ==========
__global__ void fuse_kernel(const float* __restrict__ oh, const float* __restrict__ ov,
                            const float* __restrict__ lf, float* __restrict__ fused,
                            float* __restrict__ psum)
{
    int c = threadIdx.x;
    int pc = blockIdx.x;
    int b  = blockIdx.y;
    float s = 0.f;
    for (int i = 0; i < 32; i++) {
        int p = pc * 32 + i;
        int pv = (p % WWD) * HH + p / WWD;
        float f = oh[((size_t)(b * LSEQ + p)) * 128 + c]
                + ov[((size_t)(b * LSEQ + pv)) * 128 + c]
                + lf[((size_t)(b * PPOS + p)) * 128 + c];
        fused[((size_t)(b * PPOS + p)) * 128 + c] = f;
        s += f;
    }
    psum[((size_t)b * 98 + pc) * 128 + c] = s;
}

// ========== channel attention ==========
__global__ void attn_kernel(const float* __restrict__ psum, const float* __restrict__ fc1,
                            const float* __restrict__ fc2, float* __restrict__ attn)
{
    __shared__ float sm[BATCH][CDIM];
    __shared__ float t1[BATCH][32];
    int t = threadIdx.x;   // 256
    {
        int b = t >> 7, c = t & 127;
        float s = 0.f;
        for (int pc = 0; pc < 98; pc++) s += psum[((size_t)b * 98 + pc) * 128 + c];
        sm[b][c] = s * (1.f / (float)PPOS);
    }
    __syncthreads();
    if (t < 64) {
        int b = t >> 5, i = t & 31;
        float acc = 0.f;
        #pragma unroll 4
        for (int c = 0; c < CDIM; c++) acc = fmaf(sm[b][c], fc1[i * CDIM + c], acc);
        t1[b][i] = fmaxf(acc, 0.f);
    }
    __syncthreads();
    {
        int b = t >> 7, c = t & 127;
        float acc = 0.f;
        #pragma unroll
        for (int i = 0; i < 32; i++) acc = fmaf(t1[b][i], fc2[c * 32 + i], acc);
        attn[t] = 1.f / (1.f + __expf(-acc));
    }
}

// ========== final: out = fused*attn + x (transpose tile, coalesced) ==========
__global__ __launch_bounds__(256) void final_kernel(
    const float* __restrict__ fused, const float* __restrict__ attn,
    const float* __restrict__ x, float* __restrict__ out)
{
    __shared__ float sf[128][33];
    int t = threadIdx.x;
    int p0 = blockIdx.x * 32;
    int b  = blockIdx.y;
    {
        int c = t & 127, ph = t >> 7;
        #pragma unroll
        for (int pass = 0; pass < 16; pass++) {
            int pl = pass * 2 + ph;
            sf[c][pl] = fused[((size_t)(b * PPOS + p0 + pl)) * 128 + c];
        }
    }
    __syncthreads();
    int pl = t & 31, c8 = t >> 5;
    #pragma unroll
    for (int pass = 0; pass < 16; pass++) {
        int c = pass * 8 + c8;
        size_t gi = ((size_t)(b * 128 + c)) * PPOS + p0 + pl;
        out[gi] = sf[c][pl] * attn[b * 128 + c] + x[gi];
    }
}

// ============================================================================
extern "C" void kernel_launch(void* const* d_in, const int* in_sizes, int n_in,
                              void* d_out, int out_size)
{
    const float* x       = (const float*)d_in[0];
    const float* norm_hw = (const float*)d_in[1];
    const float* norm_hb = (const float*)d_in[2];
    const float* norm_vw = (const float*)d_in[3];
    const float* norm_vb = (const float*)d_in[4];
    const float* dw_w    = (const float*)d_in[5];
    const float* dw_b    = (const float*)d_in[6];
    const float* pw_w    = (const float*)d_in[7];
    const float* pw_b    = (const float*)d_in[8];
    const float* in_w0    = (const float*)d_in[9];
    const float* conv_w0  = (const float*)d_in[10];
    const float* conv_b0  = (const float*)d_in[11];
    const float* xproj_w0 = (const float*)d_in[12];
    const float* dt_w0    = (const float*)d_in[13];
    const float* dt_b0    = (const float*)d_in[14];
    const float* A_log0   = (const float*)d_in[15];
    const float* D0       = (const float*)d_in[16];
    const float* out_w0   = (const float*)d_in[17];
    const float* in_w1    = (const float*)d_in[18];
    const float* conv_w1  = (const float*)d_in[19];
    const float* conv_b1  = (const float*)d_in[20];
    const float* xproj_w1 = (const float*)d_in[21];
    const float* dt_w1    = (const float*)d_in[22];
    const float* dt_b1    = (const float*)d_in[23];
    const float* A_log1   = (const float*)d_in[24];
    const float* D1       = (const float*)d_in[25];
    const float* out_w1   = (const float*)d_in[26];
    const float* fc1     = (const float*)d_in[27];
    const float* fc2     = (const float*)d_in[28];

    void* p;
    cudaGetSymbolAddress(&p, g_xnorm); float* xnorm = (float*)p;
    cudaGetSymbolAddress(&p, g_xz);    float* xz    = (float*)p;
    cudaGetSymbolAddress(&p, g_xs);    float* xs    = (float*)p;
    cudaGetSymbolAddress(&p, g_dbl);   float* dbl   = (float*)p;
    cudaGetSymbolAddress(&p, g_dt);    float* dt    = (float*)p;
    cudaGetSymbolAddress(&p, g_ys);    float* ys    = (float*)p;
    cudaGetSymbolAddress(&p, g_o);     float* ob    = (float*)p;
    cudaGetSymbolAddress(&p, g_g);     float* gbuf  = (float*)p;
    cudaGetSymbolAddress(&p, g_lf);    float* lfb   = (float*)p;
    cudaGetSymbolAddress(&p, g_fused); float* fused = (float*)p;
    cudaGetSymbolAddress(&p, g_Pc);    float* Pc    = (float*)p;
    cudaGetSymbolAddress(&p, g_Hc);    float* Hc    = (float*)p;
    cudaGetSymbolAddress(&p, g_Hi);    float* Hi    = (float*)p;
    cudaGetSymbolAddress(&p, g_psum);  float* psum  = (float*)p;
    cudaGetSymbolAddress(&p, g_attn);  float* attn  = (float*)p;

    // local branch
    dwgelu<<<dim3(98, 2), 256>>>(x, dw_w, dw_b, gbuf);
    gemm128<<<dim3(2, 49, 1), 256>>>(gbuf, pw_w, pw_w, pw_b, pw_b, lfb,
                                     128, 128, 0, 0);
    // layernorm, both layouts
    ln_kernel<<<dim3(98, 2), 256>>>(x, norm_hw, norm_hb, norm_vw, norm_vb,
                                    xnorm, xnorm + (size_t)MR * CDIM);
    // in_proj (both dirs)
    gemm128<<<dim3(8, 49, 2), 256>>>(xnorm, in_w0, in_w1, nullptr, nullptr, xz,
                                     512, 128, (size_t)MR * CDIM, (size_t)MR * 512);
    // conv + silu
    conv_silu<<<dim3(MR * (DI / 4) / 256, 2), 256>>>(xz, conv_w0, conv_w1,
                                                     conv_b0, conv_b1, xs);
    // x_proj + dt fused
    xproj_dt<<<dim3(1, 98, 2), 256>>>(xs, xproj_w0, xproj_w1, dt_w0, dt_w1,
                                      dt_b0, dt_b1, dbl, dt);
    // selective scan (3 passes), gate fused into C
    scanA<<<dim3(NC, BATCH, 2), 256>>>(dt, xs, dbl, A_log0, A_log1, Pc, Hc);
    scanB<<<dim3(32, 2), 256>>>(Pc, Hc, Hi);
    scanC<<<dim3(NC, BATCH, 2), 256>>>(dt, xs, dbl, xz, A_log0, A_log1, D0, D1, Hi, ys);
    // out_proj
    gemm128<<<dim3(2, 49, 2), 256>>>(ys, out_w0, out_w1, nullptr, nullptr, ob,
                                     128, 256, (size_t)MR * DI, (size_t)MR * CDIM);
    // fuse + channel attention + final
    fuse_kernel<<<dim3(98, 2), 128>>>(ob, ob + (size_t)MR * CDIM, lfb, fused, psum);
    attn_kernel<<<1, 256>>>(psum, fc1, fc2, attn);
    final_kernel<<<dim3(98, 2), 256>>>(fused, attn, x, (float*)d_out);
}